// round 1
// baseline (speedup 1.0000x reference)
#include <cuda_runtime.h>
#include <math.h>

#define T_SEQ 1024
#define E_DIM 256
#define NHEAD 8
#define HDIM 32
#define HALF 16
#define BNUM 8          // B*N = 2*4
#define BH (BNUM*NHEAD) // 64

// Scratch (static device arrays; no allocation allowed)
__device__ float g_q[BNUM * T_SEQ * E_DIM];   // [bh][t][d] : ((bn*NHEAD+h)*T + t)*32 + d
__device__ float g_k[BNUM * T_SEQ * E_DIM];
__device__ float g_v[BNUM * T_SEQ * E_DIM];
__device__ float g_att[BNUM * T_SEQ * E_DIM]; // [bn][t][e]
__device__ float g_cos[T_SEQ * HALF];
__device__ float g_sin[T_SEQ * HALF];

// ---------------------------------------------------------------------------
// RoPE table: fp64 trig so large-angle argument reduction matches reference
// ---------------------------------------------------------------------------
__global__ void rope_table_kernel() {
    int i = blockIdx.x * blockDim.x + threadIdx.x;
    if (i < T_SEQ * HALF) {
        int t = i / HALF;
        int f = i % HALF;
        double inv = pow(10000.0, -(double)f / 16.0);
        double ang = (double)t * inv;
        g_cos[i] = (float)cos(ang);
        g_sin[i] = (float)sin(ang);
    }
}

// ---------------------------------------------------------------------------
// Fused QKV GEMM + RoPE. 8 rows per block, 256 threads (thread = one column
// of each of q/k/v). x rows staged in shared; w read once per block per elem.
// ---------------------------------------------------------------------------
#define QKV_ROWS 8
__global__ __launch_bounds__(256) void qkv_rope_kernel(
    const float* __restrict__ inp,   // [B, T, 4, E]
    const float* __restrict__ w,     // [E, 3E]
    const float* __restrict__ bias)  // [3E]
{
    __shared__ float sx[QKV_ROWS][E_DIM];
    __shared__ float sq[QKV_ROWS][E_DIM];
    __shared__ float sk[QKV_ROWS][E_DIM];

    const int tid = threadIdx.x;
    const int r0 = blockIdx.x * QKV_ROWS;   // global row (bn*T + t)
    const int bn = r0 / T_SEQ;              // constant across the 8 rows
    const int t0 = r0 % T_SEQ;
    const int b  = bn >> 2;                 // bn / 4
    const int n  = bn & 3;

    // load 8 input rows: x[bn][t][e] = inp[((b*T + t)*4 + n)*E + e]
    #pragma unroll
    for (int rr = 0; rr < QKV_ROWS; rr++) {
        sx[rr][tid] = inp[(((size_t)(b * T_SEQ + t0 + rr) * 4) + n) * E_DIM + tid];
    }
    __syncthreads();

    float accq[QKV_ROWS], acck[QKV_ROWS], accv[QKV_ROWS];
    const float bq = bias[tid];
    const float bk = bias[E_DIM + tid];
    const float bv = bias[2 * E_DIM + tid];
    #pragma unroll
    for (int rr = 0; rr < QKV_ROWS; rr++) { accq[rr] = bq; acck[rr] = bk; accv[rr] = bv; }

    for (int e = 0; e < E_DIM; e++) {
        const float wq = w[e * 768 + tid];
        const float wk = w[e * 768 + E_DIM + tid];
        const float wv = w[e * 768 + 2 * E_DIM + tid];
        #pragma unroll
        for (int rr = 0; rr < QKV_ROWS; rr++) {
            const float xe = sx[rr][e];
            accq[rr] = fmaf(xe, wq, accq[rr]);
            acck[rr] = fmaf(xe, wk, acck[rr]);
            accv[rr] = fmaf(xe, wv, accv[rr]);
        }
    }

    #pragma unroll
    for (int rr = 0; rr < QKV_ROWS; rr++) { sq[rr][tid] = accq[rr]; sk[rr][tid] = acck[rr]; }
    __syncthreads();

    // RoPE + write out in attention-friendly layout [bh][t][d]
    const int h  = tid >> 5;
    const int dd = tid & 31;
    const int f  = dd & 15;
    const int partner = (dd < HALF) ? (tid + HALF) : (tid - HALF);
    const float sgn = (dd < HALF) ? -1.0f : 1.0f;

    #pragma unroll
    for (int rr = 0; rr < QKV_ROWS; rr++) {
        const int t = t0 + rr;
        const float c = g_cos[t * HALF + f];
        const float s = g_sin[t * HALF + f];
        const float qv = sq[rr][tid], kv = sk[rr][tid];
        const float qp = sq[rr][partner], kp = sk[rr][partner];
        const float qo = qv * c + sgn * qp * s;
        const float ko = kv * c + sgn * kp * s;
        const size_t base = ((size_t)(bn * NHEAD + h) * T_SEQ + t) * HDIM + dd;
        g_q[base] = qo;
        g_k[base] = ko;
        g_v[base] = accv[rr];
    }
}

// ---------------------------------------------------------------------------
// Flash attention, fp32. 128 queries per block (one per thread), K/V tiles
// of 64 in shared (all reads warp-broadcast). Causal tile skipping.
// ---------------------------------------------------------------------------
#define TQ 128
#define TK 64
__global__ __launch_bounds__(TQ) void attn_kernel() {
    const int qt  = 7 - blockIdx.x;         // heavy tiles first
    const int bh  = blockIdx.y;
    const int tid = threadIdx.x;
    const int qrow = qt * TQ + tid;

    __shared__ float Ks[TK][HDIM];
    __shared__ float Vs[TK][HDIM];

    const float scale = 0.17677669529663687f; // 1/sqrt(32)
    float q[HDIM];
    {
        const float4* qp = (const float4*)(g_q + ((size_t)bh * T_SEQ + qrow) * HDIM);
        #pragma unroll
        for (int i = 0; i < HDIM / 4; i++) {
            float4 v = qp[i];
            q[4*i+0] = v.x * scale; q[4*i+1] = v.y * scale;
            q[4*i+2] = v.z * scale; q[4*i+3] = v.w * scale;
        }
    }

    float o[HDIM];
    #pragma unroll
    for (int d = 0; d < HDIM; d++) o[d] = 0.0f;
    float m = -1e30f, l = 0.0f;

    const int nkt = 2 * (qt + 1);           // key tiles covering causal span
    for (int kt = 0; kt < nkt; kt++) {
        const int k0 = kt * TK;
        // cooperative tile load (rows contiguous in memory)
        const float4* ksrc = (const float4*)(g_k + ((size_t)bh * T_SEQ + k0) * HDIM);
        const float4* vsrc = (const float4*)(g_v + ((size_t)bh * T_SEQ + k0) * HDIM);
        float4* kd = (float4*)&Ks[0][0];
        float4* vd = (float4*)&Vs[0][0];
        #pragma unroll
        for (int i = tid; i < TK * HDIM / 4; i += TQ) { kd[i] = ksrc[i]; vd[i] = vsrc[i]; }
        __syncthreads();

        float s[TK];
        #pragma unroll
        for (int j = 0; j < TK; j++) {
            float acc = 0.0f;
            #pragma unroll
            for (int d = 0; d < HDIM; d++) acc = fmaf(q[d], Ks[j][d], acc);
            s[j] = (k0 + j <= qrow) ? acc : -1e30f;
        }

        float mt = m;
        #pragma unroll
        for (int j = 0; j < TK; j++) mt = fmaxf(mt, s[j]);
        const float alpha = __expf(m - mt);
        m = mt;
        l *= alpha;
        #pragma unroll
        for (int d = 0; d < HDIM; d++) o[d] *= alpha;

        #pragma unroll
        for (int j = 0; j < TK; j++) {
            const float p = __expf(s[j] - m);
            l += p;
            #pragma unroll
            for (int d = 0; d < HDIM; d++) o[d] = fmaf(p, Vs[j][d], o[d]);
        }
        __syncthreads();
    }

    const float inv = 1.0f / l;
    const int bn = bh >> 3, h = bh & 7;
    float* outp = g_att + ((size_t)(bn * T_SEQ + qrow)) * E_DIM + h * HDIM;
    #pragma unroll
    for (int d = 0; d < HDIM; d++) outp[d] = o[d] * inv;
}

// ---------------------------------------------------------------------------
// Output projection + transpose back to [B, T, N, E]
// ---------------------------------------------------------------------------
__global__ __launch_bounds__(256) void proj_kernel(
    const float* __restrict__ w,     // [E, E]
    const float* __restrict__ bias,  // [E]
    float* __restrict__ out)         // [B, T, 4, E]
{
    __shared__ float sx[QKV_ROWS][E_DIM];
    const int tid = threadIdx.x;
    const int r0 = blockIdx.x * QKV_ROWS;
    const int bn = r0 / T_SEQ;
    const int t0 = r0 % T_SEQ;
    const int b  = bn >> 2;
    const int n  = bn & 3;

    #pragma unroll
    for (int rr = 0; rr < QKV_ROWS; rr++)
        sx[rr][tid] = g_att[(size_t)(r0 + rr) * E_DIM + tid];
    __syncthreads();

    float acc[QKV_ROWS];
    const float bb = bias[tid];
    #pragma unroll
    for (int rr = 0; rr < QKV_ROWS; rr++) acc[rr] = bb;

    for (int e = 0; e < E_DIM; e++) {
        const float we = w[e * E_DIM + tid];
        #pragma unroll
        for (int rr = 0; rr < QKV_ROWS; rr++)
            acc[rr] = fmaf(sx[rr][e], we, acc[rr]);
    }

    #pragma unroll
    for (int rr = 0; rr < QKV_ROWS; rr++) {
        const int t = t0 + rr;
        out[(((size_t)(b * T_SEQ + t) * 4) + n) * E_DIM + tid] = acc[rr];
    }
}

// ---------------------------------------------------------------------------
extern "C" void kernel_launch(void* const* d_in, const int* in_sizes, int n_in,
                              void* d_out, int out_size) {
    const float* inp    = (const float*)d_in[0];
    const float* w_attn = (const float*)d_in[1];
    const float* b_attn = (const float*)d_in[2];
    const float* w_proj = (const float*)d_in[3];
    const float* b_proj = (const float*)d_in[4];
    float* out = (float*)d_out;

    rope_table_kernel<<<(T_SEQ * HALF + 255) / 256, 256>>>();
    qkv_rope_kernel<<<BNUM * T_SEQ / QKV_ROWS, 256>>>(inp, w_attn, b_attn);
    attn_kernel<<<dim3(8, BH), TQ>>>();
    proj_kernel<<<BNUM * T_SEQ / QKV_ROWS, 256>>>(w_proj, b_proj, out);
}

// round 2
// speedup vs baseline: 1.1188x; 1.1188x over previous
#include <cuda_runtime.h>
#include <math.h>

#define T_SEQ 1024
#define E_DIM 256
#define NHEAD 8
#define HDIM 32
#define HALF 16
#define BNUM 8          // B*N = 2*4
#define BH (BNUM*NHEAD) // 64

typedef unsigned long long ull;

// Scratch (static device arrays; no allocation allowed)
__device__ float g_q[BNUM * T_SEQ * E_DIM];   // [bh][t][d]
__device__ float g_k[BNUM * T_SEQ * E_DIM];
__device__ float g_v[BNUM * T_SEQ * E_DIM];
__device__ float g_att[BNUM * T_SEQ * E_DIM]; // [bn][t][e]
__device__ float g_cos[T_SEQ * HALF];
__device__ float g_sin[T_SEQ * HALF];

// ---------------------------------------------------------------------------
// f32x2 packed-math helpers (Blackwell FFMA2 path; ptxas won't auto-fuse)
// ---------------------------------------------------------------------------
__device__ __forceinline__ ull pack2(float lo, float hi) {
    ull r;
    asm("mov.b64 %0, {%1, %2};" : "=l"(r) : "f"(lo), "f"(hi));
    return r;
}
__device__ __forceinline__ void unpack2(ull v, float& lo, float& hi) {
    asm("mov.b64 {%0, %1}, %2;" : "=f"(lo), "=f"(hi) : "l"(v));
}
__device__ __forceinline__ ull fma2(ull a, ull b, ull c) {
    ull d;
    asm("fma.rn.f32x2 %0, %1, %2, %3;" : "=l"(d) : "l"(a), "l"(b), "l"(c));
    return d;
}
__device__ __forceinline__ ull mul2(ull a, ull b) {
    ull d;
    asm("mul.rn.f32x2 %0, %1, %2;" : "=l"(d) : "l"(a), "l"(b));
    return d;
}

// ---------------------------------------------------------------------------
// RoPE table: fp64 trig so large-angle argument reduction matches reference
// ---------------------------------------------------------------------------
__global__ void rope_table_kernel() {
    int i = blockIdx.x * blockDim.x + threadIdx.x;
    if (i < T_SEQ * HALF) {
        int t = i / HALF;
        int f = i % HALF;
        double inv = pow(10000.0, -(double)f / 16.0);
        double ang = (double)t * inv;
        g_cos[i] = (float)cos(ang);
        g_sin[i] = (float)sin(ang);
    }
}

// ---------------------------------------------------------------------------
// Fused QKV GEMM + RoPE. 8 rows per block, 256 threads. x staged TRANSPOSED
// in shared so row-pairs are contiguous -> LDS.128 feeds packed f32x2 FMA.
// ---------------------------------------------------------------------------
#define QKV_ROWS 8
__global__ __launch_bounds__(256) void qkv_rope_kernel(
    const float* __restrict__ inp,   // [B, T, 4, E]
    const float* __restrict__ w,     // [E, 3E]
    const float* __restrict__ bias)  // [3E]
{
    __shared__ __align__(16) float sxT[E_DIM][QKV_ROWS]; // transposed x
    __shared__ __align__(16) float sq[QKV_ROWS][E_DIM];
    __shared__ __align__(16) float sk[QKV_ROWS][E_DIM];

    const int tid = threadIdx.x;
    const int r0 = blockIdx.x * QKV_ROWS;
    const int bn = r0 / T_SEQ;
    const int t0 = r0 % T_SEQ;
    const int b  = bn >> 2;
    const int n  = bn & 3;

    #pragma unroll
    for (int rr = 0; rr < QKV_ROWS; rr++) {
        sxT[tid][rr] = inp[(((size_t)(b * T_SEQ + t0 + rr) * 4) + n) * E_DIM + tid];
    }
    __syncthreads();

    const float bq = bias[tid];
    const float bk = bias[E_DIM + tid];
    const float bv = bias[2 * E_DIM + tid];
    ull aq[4], ak[4], av[4];
    #pragma unroll
    for (int p = 0; p < 4; p++) { aq[p] = pack2(bq, bq); ak[p] = pack2(bk, bk); av[p] = pack2(bv, bv); }

    #pragma unroll 4
    for (int e = 0; e < E_DIM; e++) {
        const float wq = w[e * 768 + tid];
        const float wk = w[e * 768 + E_DIM + tid];
        const float wv = w[e * 768 + 2 * E_DIM + tid];
        const ull wq2 = pack2(wq, wq), wk2 = pack2(wk, wk), wv2 = pack2(wv, wv);
        const ulonglong2* xp = (const ulonglong2*)&sxT[e][0];
        const ulonglong2 x01 = xp[0];   // rows (0,1),(2,3)
        const ulonglong2 x23 = xp[1];   // rows (4,5),(6,7)
        aq[0] = fma2(x01.x, wq2, aq[0]); aq[1] = fma2(x01.y, wq2, aq[1]);
        aq[2] = fma2(x23.x, wq2, aq[2]); aq[3] = fma2(x23.y, wq2, aq[3]);
        ak[0] = fma2(x01.x, wk2, ak[0]); ak[1] = fma2(x01.y, wk2, ak[1]);
        ak[2] = fma2(x23.x, wk2, ak[2]); ak[3] = fma2(x23.y, wk2, ak[3]);
        av[0] = fma2(x01.x, wv2, av[0]); av[1] = fma2(x01.y, wv2, av[1]);
        av[2] = fma2(x23.x, wv2, av[2]); av[3] = fma2(x23.y, wv2, av[3]);
    }

    float vv[QKV_ROWS];
    #pragma unroll
    for (int p = 0; p < 4; p++) {
        float f0, f1;
        unpack2(aq[p], f0, f1); sq[2 * p][tid] = f0; sq[2 * p + 1][tid] = f1;
        unpack2(ak[p], f0, f1); sk[2 * p][tid] = f0; sk[2 * p + 1][tid] = f1;
        unpack2(av[p], vv[2 * p], vv[2 * p + 1]);
    }
    __syncthreads();

    // RoPE + write out in attention-friendly layout [bh][t][d]
    const int h  = tid >> 5;
    const int dd = tid & 31;
    const int f  = dd & 15;
    const int partner = (dd < HALF) ? (tid + HALF) : (tid - HALF);
    const float sgn = (dd < HALF) ? -1.0f : 1.0f;

    #pragma unroll
    for (int rr = 0; rr < QKV_ROWS; rr++) {
        const int t = t0 + rr;
        const float c = g_cos[t * HALF + f];
        const float s = g_sin[t * HALF + f];
        const float qv = sq[rr][tid], kv = sk[rr][tid];
        const float qp = sq[rr][partner], kp = sk[rr][partner];
        const float qo = qv * c + sgn * qp * s;
        const float ko = kv * c + sgn * kp * s;
        const size_t base = ((size_t)(bn * NHEAD + h) * T_SEQ + t) * HDIM + dd;
        g_q[base] = qo;
        g_k[base] = ko;
        g_v[base] = vv[rr];
    }
}

// ---------------------------------------------------------------------------
// Flash attention, fp32 via packed f32x2. 128 queries/block (1 per thread),
// K/V tiles of 32 in shared (all reads broadcast / LDS.128).
// ---------------------------------------------------------------------------
#define TQ 128
#define TK 32
__global__ __launch_bounds__(TQ) void attn_kernel() {
    const int qt  = 7 - blockIdx.x;         // heavy tiles first
    const int bh  = blockIdx.y;
    const int tid = threadIdx.x;
    const int qrow = qt * TQ + tid;

    __shared__ __align__(16) float Ks[TK][HDIM];
    __shared__ __align__(16) float Vs[TK][HDIM];

    const float scale = 0.17677669529663687f; // 1/sqrt(32)
    const ull scale2 = pack2(scale, scale);

    ull qd[16];
    {
        const ull* qp = (const ull*)(g_q + ((size_t)bh * T_SEQ + qrow) * HDIM);
        #pragma unroll
        for (int i = 0; i < 16; i++) qd[i] = mul2(qp[i], scale2);
    }

    ull od[16];
    #pragma unroll
    for (int i = 0; i < 16; i++) od[i] = 0ull;
    float m = -1e30f, l = 0.0f;

    const int nkt = 4 * (qt + 1);           // key tiles covering causal span
    for (int kt = 0; kt < nkt; kt++) {
        const int k0 = kt * TK;
        const float4* ksrc = (const float4*)(g_k + ((size_t)bh * T_SEQ + k0) * HDIM);
        const float4* vsrc = (const float4*)(g_v + ((size_t)bh * T_SEQ + k0) * HDIM);
        float4* kd = (float4*)&Ks[0][0];
        float4* vd = (float4*)&Vs[0][0];
        #pragma unroll
        for (int i = tid; i < TK * HDIM / 4; i += TQ) { kd[i] = ksrc[i]; vd[i] = vsrc[i]; }
        __syncthreads();

        float s[TK];
        #pragma unroll
        for (int j = 0; j < TK; j++) {
            ull acc = 0ull;
            const ulonglong2* kp = (const ulonglong2*)&Ks[j][0];
            #pragma unroll
            for (int i = 0; i < 8; i++) {
                const ulonglong2 kk = kp[i];
                acc = fma2(qd[2 * i], kk.x, acc);
                acc = fma2(qd[2 * i + 1], kk.y, acc);
            }
            float lo, hi;
            unpack2(acc, lo, hi);
            s[j] = (k0 + j <= qrow) ? (lo + hi) : -1e30f;
        }

        float mt = m;
        #pragma unroll
        for (int j = 0; j < TK; j++) mt = fmaxf(mt, s[j]);
        const float alpha = __expf(m - mt);
        m = mt;
        l *= alpha;
        const ull alpha2 = pack2(alpha, alpha);
        #pragma unroll
        for (int i = 0; i < 16; i++) od[i] = mul2(od[i], alpha2);

        #pragma unroll
        for (int j = 0; j < TK; j++) {
            const float p = __expf(s[j] - m);
            l += p;
            const ull p2 = pack2(p, p);
            const ulonglong2* vp = (const ulonglong2*)&Vs[j][0];
            #pragma unroll
            for (int i = 0; i < 8; i++) {
                const ulonglong2 vvv = vp[i];
                od[2 * i]     = fma2(p2, vvv.x, od[2 * i]);
                od[2 * i + 1] = fma2(p2, vvv.y, od[2 * i + 1]);
            }
        }
        __syncthreads();
    }

    const float inv = 1.0f / l;
    const ull inv2 = pack2(inv, inv);
    const int bn = bh >> 3, h = bh & 7;
    ull* outp = (ull*)(g_att + ((size_t)(bn * T_SEQ + qrow)) * E_DIM + h * HDIM);
    #pragma unroll
    for (int i = 0; i < 16; i++) outp[i] = mul2(od[i], inv2);
}

// ---------------------------------------------------------------------------
// Output projection + transpose back to [B, T, N, E]. 16 rows/block, f32x2.
// ---------------------------------------------------------------------------
#define PROJ_ROWS 16
__global__ __launch_bounds__(256) void proj_kernel(
    const float* __restrict__ w,     // [E, E]
    const float* __restrict__ bias,  // [E]
    float* __restrict__ out)         // [B, T, 4, E]
{
    __shared__ __align__(16) float sxT[E_DIM][PROJ_ROWS];
    const int tid = threadIdx.x;
    const int r0 = blockIdx.x * PROJ_ROWS;
    const int bn = r0 / T_SEQ;
    const int t0 = r0 % T_SEQ;
    const int b  = bn >> 2;
    const int n  = bn & 3;

    #pragma unroll
    for (int rr = 0; rr < PROJ_ROWS; rr++)
        sxT[tid][rr] = g_att[(size_t)(r0 + rr) * E_DIM + tid];
    __syncthreads();

    const float bb = bias[tid];
    ull acc[8];
    #pragma unroll
    for (int p = 0; p < 8; p++) acc[p] = pack2(bb, bb);

    #pragma unroll 4
    for (int e = 0; e < E_DIM; e++) {
        const float we = w[e * E_DIM + tid];
        const ull we2 = pack2(we, we);
        const ulonglong2* xp = (const ulonglong2*)&sxT[e][0];
        #pragma unroll
        for (int q = 0; q < 4; q++) {
            const ulonglong2 xx = xp[q];
            acc[2 * q]     = fma2(xx.x, we2, acc[2 * q]);
            acc[2 * q + 1] = fma2(xx.y, we2, acc[2 * q + 1]);
        }
    }

    #pragma unroll
    for (int p = 0; p < 8; p++) {
        float f0, f1;
        unpack2(acc[p], f0, f1);
        const int ta = t0 + 2 * p, tb = t0 + 2 * p + 1;
        out[(((size_t)(b * T_SEQ + ta) * 4) + n) * E_DIM + tid] = f0;
        out[(((size_t)(b * T_SEQ + tb) * 4) + n) * E_DIM + tid] = f1;
    }
}

// ---------------------------------------------------------------------------
extern "C" void kernel_launch(void* const* d_in, const int* in_sizes, int n_in,
                              void* d_out, int out_size) {
    const float* inp    = (const float*)d_in[0];
    const float* w_attn = (const float*)d_in[1];
    const float* b_attn = (const float*)d_in[2];
    const float* w_proj = (const float*)d_in[3];
    const float* b_proj = (const float*)d_in[4];
    float* out = (float*)d_out;

    rope_table_kernel<<<(T_SEQ * HALF + 255) / 256, 256>>>();
    qkv_rope_kernel<<<BNUM * T_SEQ / QKV_ROWS, 256>>>(inp, w_attn, b_attn);
    attn_kernel<<<dim3(8, BH), TQ>>>();
    proj_kernel<<<BNUM * T_SEQ / PROJ_ROWS, 256>>>(w_proj, b_proj, out);
}

// round 3
// speedup vs baseline: 1.2172x; 1.0880x over previous
#include <cuda_runtime.h>
#include <math.h>

#define T_SEQ 1024
#define E_DIM 256
#define NHEAD 8
#define HDIM 32
#define HALF 16
#define BNUM 8          // B*N = 2*4
#define BH (BNUM*NHEAD) // 64
#define ROWS_TOT (BNUM*T_SEQ)   // 8192

typedef unsigned long long ull;

// Scratch (static device arrays; no allocation allowed)
__device__ float g_q[BNUM * T_SEQ * E_DIM];     // [bh][t][d]
__device__ float g_k[BNUM * T_SEQ * E_DIM];
__device__ float g_v[BNUM * T_SEQ * E_DIM];
__device__ float g_attT[E_DIM * ROWS_TOT];      // TRANSPOSED: [e][bn*T + t]
__device__ float g_po[2 * BH * T_SEQ * HDIM];   // split-K partial o (unnormalized)
__device__ float g_pm[2 * BH * T_SEQ];          // split-K partial max
__device__ float g_pl[2 * BH * T_SEQ];          // split-K partial sum
__device__ float g_cos[T_SEQ * HALF];
__device__ float g_sin[T_SEQ * HALF];

// ---------------------------------------------------------------------------
// f32x2 packed-math helpers (Blackwell FFMA2 path; ptxas won't auto-fuse)
// ---------------------------------------------------------------------------
__device__ __forceinline__ ull pack2(float lo, float hi) {
    ull r;
    asm("mov.b64 %0, {%1, %2};" : "=l"(r) : "f"(lo), "f"(hi));
    return r;
}
__device__ __forceinline__ void unpack2(ull v, float& lo, float& hi) {
    asm("mov.b64 {%0, %1}, %2;" : "=f"(lo), "=f"(hi) : "l"(v));
}
__device__ __forceinline__ ull fma2(ull a, ull b, ull c) {
    ull d;
    asm("fma.rn.f32x2 %0, %1, %2, %3;" : "=l"(d) : "l"(a), "l"(b), "l"(c));
    return d;
}
__device__ __forceinline__ ull mul2(ull a, ull b) {
    ull d;
    asm("mul.rn.f32x2 %0, %1, %2;" : "=l"(d) : "l"(a), "l"(b));
    return d;
}

// ---------------------------------------------------------------------------
// RoPE table. fp64 used ONLY for the 16 inv_freq pows (per block, shared) and
// a cheap range reduction; trig is fp32 on reduced args (fast-math safe).
// ---------------------------------------------------------------------------
__global__ __launch_bounds__(256) void rope_table_kernel() {
    __shared__ double s_inv[HALF];
    if (threadIdx.x < HALF) {
        s_inv[threadIdx.x] = pow(10000.0, -(double)threadIdx.x / 16.0);
    }
    __syncthreads();
    int i = blockIdx.x * blockDim.x + threadIdx.x;   // 64 blocks * 256
    int t = i >> 4;
    int f = i & 15;
    // fp32 angle exactly as the reference computes it
    float angf = (float)t * (float)s_inv[f];
    // range-reduce in double (few DFMA), then accurate fp32 trig
    double ad = (double)angf;
    double k  = rint(ad * 0.15915494309189535);      // 1/(2*pi)
    double r  = ad - k * 6.283185307179586;
    float rf  = (float)r;
    g_cos[i] = cosf(rf);
    g_sin[i] = sinf(rf);
}

// ---------------------------------------------------------------------------
// Fused QKV GEMM + RoPE. 16 rows/block, 256 threads (1 output col each).
// x staged transposed in shared; RoPE partner exchange via shfl_xor(16).
// ---------------------------------------------------------------------------
#define QKV_ROWS 16
__global__ __launch_bounds__(256, 2) void qkv_rope_kernel(
    const float* __restrict__ inp,   // [B, T, 4, E]
    const float* __restrict__ w,     // [E, 3E]
    const float* __restrict__ bias)  // [3E]
{
    __shared__ __align__(16) float sxT[E_DIM][QKV_ROWS]; // 16KB transposed x

    const int tid = threadIdx.x;
    const int r0 = blockIdx.x * QKV_ROWS;
    const int bn = r0 / T_SEQ;
    const int t0 = r0 % T_SEQ;
    const int b  = bn >> 2;
    const int n  = bn & 3;

    #pragma unroll
    for (int rr = 0; rr < QKV_ROWS; rr++) {
        sxT[tid][rr] = inp[(((size_t)(b * T_SEQ + t0 + rr) * 4) + n) * E_DIM + tid];
    }
    __syncthreads();

    const float bq = bias[tid];
    const float bk = bias[E_DIM + tid];
    const float bv = bias[2 * E_DIM + tid];
    ull aq[8], ak[8], av[8];
    #pragma unroll
    for (int p = 0; p < 8; p++) { aq[p] = pack2(bq, bq); ak[p] = pack2(bk, bk); av[p] = pack2(bv, bv); }

    #pragma unroll 4
    for (int e = 0; e < E_DIM; e++) {
        const float wq = w[e * 768 + tid];
        const float wk = w[e * 768 + E_DIM + tid];
        const float wv = w[e * 768 + 2 * E_DIM + tid];
        const ull wq2 = pack2(wq, wq), wk2 = pack2(wk, wk), wv2 = pack2(wv, wv);
        const ulonglong2* xp = (const ulonglong2*)&sxT[e][0];
        const ulonglong2 x0 = xp[0], x1 = xp[1], x2 = xp[2], x3 = xp[3];
        aq[0] = fma2(x0.x, wq2, aq[0]); aq[1] = fma2(x0.y, wq2, aq[1]);
        aq[2] = fma2(x1.x, wq2, aq[2]); aq[3] = fma2(x1.y, wq2, aq[3]);
        aq[4] = fma2(x2.x, wq2, aq[4]); aq[5] = fma2(x2.y, wq2, aq[5]);
        aq[6] = fma2(x3.x, wq2, aq[6]); aq[7] = fma2(x3.y, wq2, aq[7]);
        ak[0] = fma2(x0.x, wk2, ak[0]); ak[1] = fma2(x0.y, wk2, ak[1]);
        ak[2] = fma2(x1.x, wk2, ak[2]); ak[3] = fma2(x1.y, wk2, ak[3]);
        ak[4] = fma2(x2.x, wk2, ak[4]); ak[5] = fma2(x2.y, wk2, ak[5]);
        ak[6] = fma2(x3.x, wk2, ak[6]); ak[7] = fma2(x3.y, wk2, ak[7]);
        av[0] = fma2(x0.x, wv2, av[0]); av[1] = fma2(x0.y, wv2, av[1]);
        av[2] = fma2(x1.x, wv2, av[2]); av[3] = fma2(x1.y, wv2, av[3]);
        av[4] = fma2(x2.x, wv2, av[4]); av[5] = fma2(x2.y, wv2, av[5]);
        av[6] = fma2(x3.x, wv2, av[6]); av[7] = fma2(x3.y, wv2, av[7]);
    }

    // RoPE entirely in registers: partner lane is tid^16 (same warp, same h)
    const int h  = tid >> 5;
    const int dd = tid & 31;
    const int f  = dd & 15;
    const float sgn = (dd < HALF) ? -1.0f : 1.0f;
    const size_t rowbase = ((size_t)(bn * NHEAD + h) * T_SEQ + t0) * HDIM + dd;

    #pragma unroll
    for (int p = 0; p < 8; p++) {
        float q0, q1, k0, k1, v0, v1;
        unpack2(aq[p], q0, q1);
        unpack2(ak[p], k0, k1);
        unpack2(av[p], v0, v1);
        const float qp0 = __shfl_xor_sync(0xffffffffu, q0, 16);
        const float qp1 = __shfl_xor_sync(0xffffffffu, q1, 16);
        const float kp0 = __shfl_xor_sync(0xffffffffu, k0, 16);
        const float kp1 = __shfl_xor_sync(0xffffffffu, k1, 16);
        const int t = t0 + 2 * p;
        const float c0 = g_cos[t * HALF + f],       s0 = g_sin[t * HALF + f];
        const float c1 = g_cos[(t + 1) * HALF + f], s1 = g_sin[(t + 1) * HALF + f];
        const size_t base = rowbase + (size_t)(2 * p) * HDIM;
        g_q[base]        = q0 * c0 + sgn * qp0 * s0;
        g_k[base]        = k0 * c0 + sgn * kp0 * s0;
        g_v[base]        = v0;
        g_q[base + HDIM] = q1 * c1 + sgn * qp1 * s1;
        g_k[base + HDIM] = k1 * c1 + sgn * kp1 * s1;
        g_v[base + HDIM] = v1;
    }
}

// ---------------------------------------------------------------------------
// Flash attention stage 1: split-K over 2 key halves. Each block handles
// (q-tile, bh, split); writes unnormalized partial o plus (m, l).
// ---------------------------------------------------------------------------
#define TQ 128
#define TK 32
#define KSPLIT 512
__global__ __launch_bounds__(TQ) void attn_kernel() {
    const int qt  = 7 - blockIdx.x;         // heavy tiles first
    const int bh  = blockIdx.y;
    const int sp  = blockIdx.z;
    const int tid = threadIdx.x;
    const int qrow = qt * TQ + tid;
    const size_t pidx = ((size_t)sp * BH + bh) * T_SEQ + qrow;

    const int kbeg = sp * KSPLIT;
    const int kend = min((sp + 1) * KSPLIT, (qt + 1) * TQ);

    if (kbeg >= kend) {                     // empty split (sp=1, qt<4)
        g_pm[pidx] = -1e30f;
        g_pl[pidx] = 0.0f;
        ull* op = (ull*)(g_po + pidx * HDIM);
        #pragma unroll
        for (int i = 0; i < 16; i++) op[i] = 0ull;
        return;
    }

    __shared__ __align__(16) float Ks[TK][HDIM];
    __shared__ __align__(16) float Vs[TK][HDIM];

    const float scale = 0.17677669529663687f; // 1/sqrt(32)
    const ull scale2 = pack2(scale, scale);

    ull qd[16];
    {
        const ull* qp = (const ull*)(g_q + ((size_t)bh * T_SEQ + qrow) * HDIM);
        #pragma unroll
        for (int i = 0; i < 16; i++) qd[i] = mul2(qp[i], scale2);
    }

    ull od[16];
    #pragma unroll
    for (int i = 0; i < 16; i++) od[i] = 0ull;
    float m = -1e30f, l = 0.0f;

    for (int k0 = kbeg; k0 < kend; k0 += TK) {
        const float4* ksrc = (const float4*)(g_k + ((size_t)bh * T_SEQ + k0) * HDIM);
        const float4* vsrc = (const float4*)(g_v + ((size_t)bh * T_SEQ + k0) * HDIM);
        float4* kd = (float4*)&Ks[0][0];
        float4* vd = (float4*)&Vs[0][0];
        #pragma unroll
        for (int i = tid; i < TK * HDIM / 4; i += TQ) { kd[i] = ksrc[i]; vd[i] = vsrc[i]; }
        __syncthreads();

        float s[TK];
        #pragma unroll
        for (int j = 0; j < TK; j++) {
            ull acc = 0ull;
            const ulonglong2* kp = (const ulonglong2*)&Ks[j][0];
            #pragma unroll
            for (int i = 0; i < 8; i++) {
                const ulonglong2 kk = kp[i];
                acc = fma2(qd[2 * i], kk.x, acc);
                acc = fma2(qd[2 * i + 1], kk.y, acc);
            }
            float lo, hi;
            unpack2(acc, lo, hi);
            s[j] = (k0 + j <= qrow) ? (lo + hi) : -1e30f;
        }

        float mt = m;
        #pragma unroll
        for (int j = 0; j < TK; j++) mt = fmaxf(mt, s[j]);
        const float alpha = __expf(m - mt);
        m = mt;
        l *= alpha;
        const ull alpha2 = pack2(alpha, alpha);
        #pragma unroll
        for (int i = 0; i < 16; i++) od[i] = mul2(od[i], alpha2);

        #pragma unroll
        for (int j = 0; j < TK; j++) {
            const float p = __expf(s[j] - m);
            l += p;
            const ull p2 = pack2(p, p);
            const ulonglong2* vp = (const ulonglong2*)&Vs[j][0];
            #pragma unroll
            for (int i = 0; i < 8; i++) {
                const ulonglong2 vvv = vp[i];
                od[2 * i]     = fma2(p2, vvv.x, od[2 * i]);
                od[2 * i + 1] = fma2(p2, vvv.y, od[2 * i + 1]);
            }
        }
        __syncthreads();
    }

    g_pm[pidx] = m;
    g_pl[pidx] = l;
    ull* op = (ull*)(g_po + pidx * HDIM);
    #pragma unroll
    for (int i = 0; i < 16; i++) op[i] = od[i];
}

// ---------------------------------------------------------------------------
// Stage 2: merge the two split-K partials; write TRANSPOSED g_attT[e][row]
// via a shared tile so global stores are coalesced.
// ---------------------------------------------------------------------------
__global__ __launch_bounds__(TQ) void combine_kernel() {
    __shared__ float Os[HDIM][TQ + 1];   // padded: conflict-free both ways
    __shared__ float sw0[TQ], sw1[TQ], sinv[TQ];

    const int qt  = blockIdx.x;
    const int bh  = blockIdx.y;
    const int tid = threadIdx.x;
    const int qrow = qt * TQ + tid;
    const size_t p0 = ((size_t)bh) * T_SEQ + qrow;
    const size_t p1 = ((size_t)BH + bh) * T_SEQ + qrow;

    const float m0 = g_pm[p0], m1 = g_pm[p1];
    const float l0 = g_pl[p0], l1 = g_pl[p1];
    const float M  = fmaxf(m0, m1);
    const float w0 = __expf(m0 - M);
    const float w1 = __expf(m1 - M);
    sw0[tid]  = w0;
    sw1[tid]  = w1;
    sinv[tid] = 1.0f / (w0 * l0 + w1 * l1);
    __syncthreads();

    // cooperative coalesced read of both partial o tiles
    const float* o0 = g_po + (((size_t)bh) * T_SEQ + qt * TQ) * HDIM;
    const float* o1 = g_po + (((size_t)BH + bh) * T_SEQ + qt * TQ) * HDIM;
    #pragma unroll
    for (int i = 0; i < 32; i++) {
        const int idx = i * TQ + tid;      // over 128 rows * 32 dims
        const int d = idx & 31;
        const int r = idx >> 5;
        Os[d][r] = (sw0[r] * o0[idx] + sw1[r] * o1[idx]) * sinv[r];
    }
    __syncthreads();

    const int bn = bh >> 3, h = bh & 7;
    const size_t col0 = (size_t)bn * T_SEQ + qt * TQ + tid;
    #pragma unroll
    for (int i = 0; i < HDIM; i++) {
        g_attT[(size_t)(h * HDIM + i) * ROWS_TOT + col0] = Os[i][tid];
    }
}

// ---------------------------------------------------------------------------
// Output projection + transpose back to [B, T, N, E]. 32 rows/block.
// Reads transposed g_attT so the shared transpose staging is conflict-free.
// ---------------------------------------------------------------------------
#define PROJ_ROWS 32
__global__ __launch_bounds__(256, 2) void proj_kernel(
    const float* __restrict__ w,     // [E, E]
    const float* __restrict__ bias,  // [E]
    float* __restrict__ out)         // [B, T, 4, E]
{
    __shared__ __align__(16) float sxT[E_DIM][PROJ_ROWS]; // 32KB
    const int tid = threadIdx.x;
    const int r0 = blockIdx.x * PROJ_ROWS;
    const int bn = r0 / T_SEQ;
    const int t0 = r0 % T_SEQ;
    const int b  = bn >> 2;
    const int n  = bn & 3;

    // staging: 2048 float4, 8 per thread; LDG coalesced, STS conflict-free
    #pragma unroll
    for (int i = 0; i < 8; i++) {
        const int idx = tid + i * 256;
        const int e = idx >> 3;
        const int j = idx & 7;
        const float4 v = *(const float4*)(g_attT + (size_t)e * ROWS_TOT + r0 + 4 * j);
        *(float4*)&sxT[e][4 * j] = v;
    }
    __syncthreads();

    const float bb = bias[tid];
    ull acc[16];
    #pragma unroll
    for (int p = 0; p < 16; p++) acc[p] = pack2(bb, bb);

    #pragma unroll 4
    for (int e = 0; e < E_DIM; e++) {
        const float we = w[e * E_DIM + tid];
        const ull we2 = pack2(we, we);
        const ulonglong2* xp = (const ulonglong2*)&sxT[e][0];
        #pragma unroll
        for (int q = 0; q < 8; q++) {
            const ulonglong2 xx = xp[q];
            acc[2 * q]     = fma2(xx.x, we2, acc[2 * q]);
            acc[2 * q + 1] = fma2(xx.y, we2, acc[2 * q + 1]);
        }
    }

    #pragma unroll
    for (int p = 0; p < 16; p++) {
        float f0, f1;
        unpack2(acc[p], f0, f1);
        const int ta = t0 + 2 * p, tb = ta + 1;
        out[(((size_t)(b * T_SEQ + ta) * 4) + n) * E_DIM + tid] = f0;
        out[(((size_t)(b * T_SEQ + tb) * 4) + n) * E_DIM + tid] = f1;
    }
}

// ---------------------------------------------------------------------------
extern "C" void kernel_launch(void* const* d_in, const int* in_sizes, int n_in,
                              void* d_out, int out_size) {
    const float* inp    = (const float*)d_in[0];
    const float* w_attn = (const float*)d_in[1];
    const float* b_attn = (const float*)d_in[2];
    const float* w_proj = (const float*)d_in[3];
    const float* b_proj = (const float*)d_in[4];
    float* out = (float*)d_out;

    rope_table_kernel<<<T_SEQ * HALF / 256, 256>>>();
    qkv_rope_kernel<<<ROWS_TOT / QKV_ROWS, 256>>>(inp, w_attn, b_attn);
    attn_kernel<<<dim3(8, BH, 2), TQ>>>();
    combine_kernel<<<dim3(8, BH), TQ>>>();
    proj_kernel<<<ROWS_TOT / PROJ_ROWS, 256>>>(w_proj, b_proj, out);
}

// round 5
// speedup vs baseline: 1.2634x; 1.0380x over previous
#include <cuda_runtime.h>
#include <cstdint>
#include <math.h>

#define T_SEQ 1024
#define E_DIM 256
#define NHEAD 8
#define HDIM 32
#define HALF 16
#define BNUM 8          // B*N = 2*4
#define BH (BNUM*NHEAD) // 64
#define ROWS_TOT (BNUM*T_SEQ)   // 8192

typedef unsigned long long ull;

// Scratch (static device arrays; no allocation allowed)
__device__ float g_q[BNUM * T_SEQ * E_DIM];     // [bh][t][d]
__device__ float g_k[BNUM * T_SEQ * E_DIM];
__device__ float g_v[BNUM * T_SEQ * E_DIM];
__device__ float g_attT[E_DIM * ROWS_TOT];      // TRANSPOSED: [e][bn*T + t]
__device__ float g_po[2 * BH * T_SEQ * HDIM];   // split-K partial o (unnormalized)
__device__ float g_pm[2 * BH * T_SEQ];          // split-K partial max (log2 domain)
__device__ float g_pl[2 * BH * T_SEQ];          // split-K partial sum
__device__ float g_cos[T_SEQ * HALF];
__device__ float g_sin[T_SEQ * HALF];

// ---------------------------------------------------------------------------
// f32x2 packed-math helpers (Blackwell FFMA2 path; ptxas won't auto-fuse)
// ---------------------------------------------------------------------------
__device__ __forceinline__ ull pack2(float lo, float hi) {
    ull r;
    asm("mov.b64 %0, {%1, %2};" : "=l"(r) : "f"(lo), "f"(hi));
    return r;
}
__device__ __forceinline__ void unpack2(ull v, float& lo, float& hi) {
    asm("mov.b64 {%0, %1}, %2;" : "=f"(lo), "=f"(hi) : "l"(v));
}
__device__ __forceinline__ ull fma2(ull a, ull b, ull c) {
    ull d;
    asm("fma.rn.f32x2 %0, %1, %2, %3;" : "=l"(d) : "l"(a), "l"(b), "l"(c));
    return d;
}
__device__ __forceinline__ ull mul2(ull a, ull b) {
    ull d;
    asm("mul.rn.f32x2 %0, %1, %2;" : "=l"(d) : "l"(a), "l"(b));
    return d;
}

// cp.async helpers (16B)
__device__ __forceinline__ void cp_async16(uint32_t saddr, const void* gptr) {
    asm volatile("cp.async.cg.shared.global [%0], [%1], 16;" :: "r"(saddr), "l"(gptr));
}
__device__ __forceinline__ void cp_commit() {
    asm volatile("cp.async.commit_group;");
}
template <int N>
__device__ __forceinline__ void cp_wait() {
    asm volatile("cp.async.wait_group %0;" :: "n"(N));
}
__device__ __forceinline__ uint32_t smem_u32(const void* p) {
    uint32_t a;
    asm("{ .reg .u64 t; cvta.to.shared.u64 t, %1; cvt.u32.u64 %0, t; }" : "=r"(a) : "l"(p));
    return a;
}

// ---------------------------------------------------------------------------
// RoPE table. fp64 only for the 16 inv_freq pows + range reduction.
// ---------------------------------------------------------------------------
__global__ __launch_bounds__(256) void rope_table_kernel() {
    __shared__ double s_inv[HALF];
    if (threadIdx.x < HALF) {
        s_inv[threadIdx.x] = pow(10000.0, -(double)threadIdx.x / 16.0);
    }
    __syncthreads();
    int i = blockIdx.x * blockDim.x + threadIdx.x;
    int t = i >> 4;
    int f = i & 15;
    float angf = (float)t * (float)s_inv[f];       // fp32, matches reference
    double ad = (double)angf;
    double k  = rint(ad * 0.15915494309189535);
    double r  = ad - k * 6.283185307179586;
    float rf  = (float)r;
    g_cos[i] = cosf(rf);
    g_sin[i] = sinf(rf);
}

// ---------------------------------------------------------------------------
// Fused QKV GEMM + RoPE. 16 rows/block, 256 threads, 8-e w-prefetch chunks.
// ---------------------------------------------------------------------------
#define QKV_ROWS 16
__global__ __launch_bounds__(256, 2) void qkv_rope_kernel(
    const float* __restrict__ inp,   // [B, T, 4, E]
    const float* __restrict__ w,     // [E, 3E]
    const float* __restrict__ bias)  // [3E]
{
    __shared__ __align__(16) float sxT[E_DIM][QKV_ROWS]; // 16KB transposed x

    const int tid = threadIdx.x;
    const int r0 = blockIdx.x * QKV_ROWS;
    const int bn = r0 / T_SEQ;
    const int t0 = r0 % T_SEQ;
    const int b  = bn >> 2;
    const int n  = bn & 3;

    #pragma unroll
    for (int rr = 0; rr < QKV_ROWS; rr++) {
        sxT[tid][rr] = inp[(((size_t)(b * T_SEQ + t0 + rr) * 4) + n) * E_DIM + tid];
    }
    __syncthreads();

    const float bq = bias[tid];
    const float bk = bias[E_DIM + tid];
    const float bv = bias[2 * E_DIM + tid];
    ull aq[8], ak[8], av[8];
    #pragma unroll
    for (int p = 0; p < 8; p++) { aq[p] = pack2(bq, bq); ak[p] = pack2(bk, bk); av[p] = pack2(bv, bv); }

    #pragma unroll 1
    for (int e0 = 0; e0 < E_DIM; e0 += 8) {
        // batch all 24 w loads up front -> MLP 24, L2 latency amortized
        float wq[8], wk[8], wv[8];
        #pragma unroll
        for (int j = 0; j < 8; j++) {
            const float* wp = w + (e0 + j) * 768 + tid;
            wq[j] = wp[0];
            wk[j] = wp[E_DIM];
            wv[j] = wp[2 * E_DIM];
        }
        #pragma unroll
        for (int j = 0; j < 8; j++) {
            const int e = e0 + j;
            const ull wq2 = pack2(wq[j], wq[j]);
            const ull wk2 = pack2(wk[j], wk[j]);
            const ull wv2 = pack2(wv[j], wv[j]);
            const ulonglong2* xp = (const ulonglong2*)&sxT[e][0];
            const ulonglong2 x0 = xp[0], x1 = xp[1], x2 = xp[2], x3 = xp[3];
            aq[0] = fma2(x0.x, wq2, aq[0]); aq[1] = fma2(x0.y, wq2, aq[1]);
            aq[2] = fma2(x1.x, wq2, aq[2]); aq[3] = fma2(x1.y, wq2, aq[3]);
            aq[4] = fma2(x2.x, wq2, aq[4]); aq[5] = fma2(x2.y, wq2, aq[5]);
            aq[6] = fma2(x3.x, wq2, aq[6]); aq[7] = fma2(x3.y, wq2, aq[7]);
            ak[0] = fma2(x0.x, wk2, ak[0]); ak[1] = fma2(x0.y, wk2, ak[1]);
            ak[2] = fma2(x1.x, wk2, ak[2]); ak[3] = fma2(x1.y, wk2, ak[3]);
            ak[4] = fma2(x2.x, wk2, ak[4]); ak[5] = fma2(x2.y, wk2, ak[5]);
            ak[6] = fma2(x3.x, wk2, ak[6]); ak[7] = fma2(x3.y, wk2, ak[7]);
            av[0] = fma2(x0.x, wv2, av[0]); av[1] = fma2(x0.y, wv2, av[1]);
            av[2] = fma2(x1.x, wv2, av[2]); av[3] = fma2(x1.y, wv2, av[3]);
            av[4] = fma2(x2.x, wv2, av[4]); av[5] = fma2(x2.y, wv2, av[5]);
            av[6] = fma2(x3.x, wv2, av[6]); av[7] = fma2(x3.y, wv2, av[7]);
        }
    }

    // RoPE in registers: partner lane is tid^16 (same warp, same h)
    const int h  = tid >> 5;
    const int dd = tid & 31;
    const int f  = dd & 15;
    const float sgn = (dd < HALF) ? -1.0f : 1.0f;
    const size_t rowbase = ((size_t)(bn * NHEAD + h) * T_SEQ + t0) * HDIM + dd;

    #pragma unroll
    for (int p = 0; p < 8; p++) {
        float q0, q1, k0, k1, v0, v1;
        unpack2(aq[p], q0, q1);
        unpack2(ak[p], k0, k1);
        unpack2(av[p], v0, v1);
        const float qp0 = __shfl_xor_sync(0xffffffffu, q0, 16);
        const float qp1 = __shfl_xor_sync(0xffffffffu, q1, 16);
        const float kp0 = __shfl_xor_sync(0xffffffffu, k0, 16);
        const float kp1 = __shfl_xor_sync(0xffffffffu, k1, 16);
        const int t = t0 + 2 * p;
        const float c0 = g_cos[t * HALF + f],       s0 = g_sin[t * HALF + f];
        const float c1 = g_cos[(t + 1) * HALF + f], s1 = g_sin[(t + 1) * HALF + f];
        const size_t base = rowbase + (size_t)(2 * p) * HDIM;
        g_q[base]        = q0 * c0 + sgn * qp0 * s0;
        g_k[base]        = k0 * c0 + sgn * kp0 * s0;
        g_v[base]        = v0;
        g_q[base + HDIM] = q1 * c1 + sgn * qp1 * s1;
        g_k[base + HDIM] = k1 * c1 + sgn * kp1 * s1;
        g_v[base + HDIM] = v1;
    }
}

// ---------------------------------------------------------------------------
// Flash attention stage 1 (split-K x2), cp.async double-buffered K/V tiles,
// exp2-domain softmax (log2(e) folded into q scale).
// ---------------------------------------------------------------------------
#define TQ 128
#define TK 32
#define KSPLIT 512
__global__ __launch_bounds__(TQ) void attn_kernel() {
    const int qt  = 7 - blockIdx.x;         // heavy tiles first
    const int bh  = blockIdx.y;
    const int sp  = blockIdx.z;
    const int tid = threadIdx.x;
    const int qrow = qt * TQ + tid;
    const size_t pidx = ((size_t)sp * BH + bh) * T_SEQ + qrow;

    const int kbeg = sp * KSPLIT;
    const int kend = min((sp + 1) * KSPLIT, (qt + 1) * TQ);

    if (kbeg >= kend) {                     // empty split (sp=1, qt<4)
        g_pm[pidx] = -1e30f;
        g_pl[pidx] = 0.0f;
        ull* op = (ull*)(g_po + pidx * HDIM);
        #pragma unroll
        for (int i = 0; i < 16; i++) op[i] = 0ull;
        return;
    }

    __shared__ __align__(16) float Ks[2][TK][HDIM];
    __shared__ __align__(16) float Vs[2][TK][HDIM];

    // scale * log2(e): softmax computed with exp2
    const float scale = 0.17677669529663687f * 1.4426950408889634f;
    const ull scale2 = pack2(scale, scale);

    ull qd[16];
    {
        const ull* qp = (const ull*)(g_q + ((size_t)bh * T_SEQ + qrow) * HDIM);
        #pragma unroll
        for (int i = 0; i < 16; i++) qd[i] = mul2(qp[i], scale2);
    }

    ull od[16];
    #pragma unroll
    for (int i = 0; i < 16; i++) od[i] = 0ull;
    float m = -1e30f, l = 0.0f;

    const int ntiles = (kend - kbeg) / TK;

    // prologue: load tile 0 into buffer 0
    {
        const float* ksrc = g_k + ((size_t)bh * T_SEQ + kbeg) * HDIM;
        const float* vsrc = g_v + ((size_t)bh * T_SEQ + kbeg) * HDIM;
        const uint32_t kdst = smem_u32(&Ks[0][0][0]);
        const uint32_t vdst = smem_u32(&Vs[0][0][0]);
        #pragma unroll
        for (int i = 0; i < 2; i++) {
            const int off = (tid + i * TQ) * 4;          // float index
            cp_async16(kdst + off * 4, ksrc + off);
            cp_async16(vdst + off * 4, vsrc + off);
        }
        cp_commit();
    }

    for (int kt = 0; kt < ntiles; kt++) {
        const int k0 = kbeg + kt * TK;
        if (kt + 1 < ntiles) {
            const int nb = (kt + 1) & 1;
            const float* ksrc = g_k + ((size_t)bh * T_SEQ + k0 + TK) * HDIM;
            const float* vsrc = g_v + ((size_t)bh * T_SEQ + k0 + TK) * HDIM;
            const uint32_t kdst = smem_u32(&Ks[nb][0][0]);
            const uint32_t vdst = smem_u32(&Vs[nb][0][0]);
            #pragma unroll
            for (int i = 0; i < 2; i++) {
                const int off = (tid + i * TQ) * 4;
                cp_async16(kdst + off * 4, ksrc + off);
                cp_async16(vdst + off * 4, vsrc + off);
            }
            cp_commit();
            cp_wait<1>();
        } else {
            cp_wait<0>();
        }
        __syncthreads();
        const int cb = kt & 1;

        float s[TK];
        #pragma unroll
        for (int j = 0; j < TK; j++) {
            ull acc = 0ull;
            const ulonglong2* kp = (const ulonglong2*)&Ks[cb][j][0];
            #pragma unroll
            for (int i = 0; i < 8; i++) {
                const ulonglong2 kk = kp[i];
                acc = fma2(qd[2 * i], kk.x, acc);
                acc = fma2(qd[2 * i + 1], kk.y, acc);
            }
            float lo, hi;
            unpack2(acc, lo, hi);
            s[j] = (k0 + j <= qrow) ? (lo + hi) : -1e30f;
        }

        float mt = m;
        #pragma unroll
        for (int j = 0; j < TK; j++) mt = fmaxf(mt, s[j]);
        const float alpha = exp2f(m - mt);
        m = mt;
        l *= alpha;
        const ull alpha2 = pack2(alpha, alpha);
        #pragma unroll
        for (int i = 0; i < 16; i++) od[i] = mul2(od[i], alpha2);

        #pragma unroll
        for (int j = 0; j < TK; j++) {
            const float p = exp2f(s[j] - m);
            l += p;
            const ull p2 = pack2(p, p);
            const ulonglong2* vp = (const ulonglong2*)&Vs[cb][j][0];
            #pragma unroll
            for (int i = 0; i < 8; i++) {
                const ulonglong2 vvv = vp[i];
                od[2 * i]     = fma2(p2, vvv.x, od[2 * i]);
                od[2 * i + 1] = fma2(p2, vvv.y, od[2 * i + 1]);
            }
        }
        __syncthreads();
    }

    g_pm[pidx] = m;
    g_pl[pidx] = l;
    ull* op = (ull*)(g_po + pidx * HDIM);
    #pragma unroll
    for (int i = 0; i < 16; i++) op[i] = od[i];
}

// ---------------------------------------------------------------------------
// Stage 2: merge split-K partials; write TRANSPOSED g_attT[e][row].
// ---------------------------------------------------------------------------
__global__ __launch_bounds__(TQ) void combine_kernel() {
    __shared__ float Os[HDIM][TQ + 1];
    __shared__ float sw0[TQ], sw1[TQ], sinv[TQ];

    const int qt  = blockIdx.x;
    const int bh  = blockIdx.y;
    const int tid = threadIdx.x;
    const int qrow = qt * TQ + tid;
    const size_t p0 = ((size_t)bh) * T_SEQ + qrow;
    const size_t p1 = ((size_t)BH + bh) * T_SEQ + qrow;

    const float m0 = g_pm[p0], m1 = g_pm[p1];
    const float l0 = g_pl[p0], l1 = g_pl[p1];
    const float M  = fmaxf(m0, m1);
    const float w0 = exp2f(m0 - M);
    const float w1 = exp2f(m1 - M);
    sw0[tid]  = w0;
    sw1[tid]  = w1;
    sinv[tid] = 1.0f / (w0 * l0 + w1 * l1);
    __syncthreads();

    const float* o0 = g_po + (((size_t)bh) * T_SEQ + qt * TQ) * HDIM;
    const float* o1 = g_po + (((size_t)BH + bh) * T_SEQ + qt * TQ) * HDIM;
    #pragma unroll
    for (int i = 0; i < 32; i++) {
        const int idx = i * TQ + tid;
        const int d = idx & 31;
        const int r = idx >> 5;
        Os[d][r] = (sw0[r] * o0[idx] + sw1[r] * o1[idx]) * sinv[r];
    }
    __syncthreads();

    const int bn = bh >> 3, h = bh & 7;
    const size_t col0 = (size_t)bn * T_SEQ + qt * TQ + tid;
    #pragma unroll
    for (int i = 0; i < HDIM; i++) {
        g_attT[(size_t)(h * HDIM + i) * ROWS_TOT + col0] = Os[i][tid];
    }
}

// ---------------------------------------------------------------------------
// Output projection + transpose back to [B, T, N, E]. 32 rows/block,
// 8-e w-prefetch chunks.
// ---------------------------------------------------------------------------
#define PROJ_ROWS 32
__global__ __launch_bounds__(256, 2) void proj_kernel(
    const float* __restrict__ w,     // [E, E]
    const float* __restrict__ bias,  // [E]
    float* __restrict__ out)         // [B, T, 4, E]
{
    __shared__ __align__(16) float sxT[E_DIM][PROJ_ROWS]; // 32KB
    const int tid = threadIdx.x;
    const int r0 = blockIdx.x * PROJ_ROWS;
    const int bn = r0 / T_SEQ;
    const int t0 = r0 % T_SEQ;
    const int b  = bn >> 2;
    const int n  = bn & 3;

    #pragma unroll
    for (int i = 0; i < 8; i++) {
        const int idx = tid + i * 256;
        const int e = idx >> 3;
        const int j = idx & 7;
        const float4 v = *(const float4*)(g_attT + (size_t)e * ROWS_TOT + r0 + 4 * j);
        *(float4*)&sxT[e][4 * j] = v;
    }
    __syncthreads();

    const float bb = bias[tid];
    ull acc[16];
    #pragma unroll
    for (int p = 0; p < 16; p++) acc[p] = pack2(bb, bb);

    #pragma unroll 1
    for (int e0 = 0; e0 < E_DIM; e0 += 8) {
        float wv[8];
        #pragma unroll
        for (int j = 0; j < 8; j++) wv[j] = w[(e0 + j) * E_DIM + tid];
        #pragma unroll
        for (int j = 0; j < 8; j++) {
            const ull we2 = pack2(wv[j], wv[j]);
            const ulonglong2* xp = (const ulonglong2*)&sxT[e0 + j][0];
            #pragma unroll
            for (int q = 0; q < 8; q++) {
                const ulonglong2 xx = xp[q];
                acc[2 * q]     = fma2(xx.x, we2, acc[2 * q]);
                acc[2 * q + 1] = fma2(xx.y, we2, acc[2 * q + 1]);
            }
        }
    }

    #pragma unroll
    for (int p = 0; p < 16; p++) {
        float f0, f1;
        unpack2(acc[p], f0, f1);
        const int ta = t0 + 2 * p, tb = ta + 1;
        out[(((size_t)(b * T_SEQ + ta) * 4) + n) * E_DIM + tid] = f0;
        out[(((size_t)(b * T_SEQ + tb) * 4) + n) * E_DIM + tid] = f1;
    }
}

// ---------------------------------------------------------------------------
extern "C" void kernel_launch(void* const* d_in, const int* in_sizes, int n_in,
                              void* d_out, int out_size) {
    const float* inp    = (const float*)d_in[0];
    const float* w_attn = (const float*)d_in[1];
    const float* b_attn = (const float*)d_in[2];
    const float* w_proj = (const float*)d_in[3];
    const float* b_proj = (const float*)d_in[4];
    float* out = (float*)d_out;

    rope_table_kernel<<<T_SEQ * HALF / 256, 256>>>();
    qkv_rope_kernel<<<ROWS_TOT / QKV_ROWS, 256>>>(inp, w_attn, b_attn);
    attn_kernel<<<dim3(8, BH, 2), TQ>>>();
    combine_kernel<<<dim3(8, BH), TQ>>>();
    proj_kernel<<<ROWS_TOT / PROJ_ROWS, 256>>>(w_proj, b_proj, out);
}